// round 14
// baseline (speedup 1.0000x reference)
#include <cuda_runtime.h>
#include <cuda_bf16.h>
#include <mma.h>
#include <cstdint>

using namespace nvcuda;

// ---------------------------------------------------------------------------
// ContrastiveSparsityLoss — wmma bf16-split (HMMA) conv + GEMM.
// R14 == R13 resubmitted (container-level infra failure, no kernel evidence):
//  - conv patch staging coalesced (xx innermost; was ci -> 8x sector fetch)
//  - w1/w2 pre-split to bf16 (hi,lo) staging-layout tables once per granularity
// ---------------------------------------------------------------------------

__device__ float g_y1[5 * 64 * 65536];    // 83.9 MB scratch
__device__ float g_z [5 * 128 * 65536];   // 167.8 MB scratch
__device__ float g_stat1[5 * 64 * 2];
__device__ float g_stat2[5 * 128 * 2];
__device__ float g_a1[5 * 64];
__device__ float g_b1[5 * 64];
__device__ float g_a2[5 * 128];
__device__ float g_b2[5 * 128];
__device__ float g_feat[6 * 5 * 128];     // [e][n][oc], e = path*3+g
__device__ __nv_bfloat162 g_w1s[9 * 64 * 64];  // [d][ci][oc] (hi,lo), Cin<=64
__device__ __nv_bfloat162 g_w2s[128 * 64];     // [oc][k]     (hi,lo)

__device__ __forceinline__ void split_bf16(float v, __nv_bfloat16& hi, __nv_bfloat16& lo) {
    hi = __float2bfloat16(v);
    lo = __float2bfloat16(v - __bfloat162float(hi));
}

// ---------------------------------------------------------------------------
// prep: pre-split weights into staging layouts (once per granularity).
// w1 [O=64][Cin][3][3] -> g_w1s[(d*Cin+ci)*64+o]; w2 [128][64] -> g_w2s.
// ---------------------------------------------------------------------------
__global__ void prep_w1_kernel(const float* __restrict__ w, int Cin)
{
    int idx = blockIdx.x * blockDim.x + threadIdx.x;   // over 9*Cin*64
    if (idx >= 9 * Cin * 64) return;
    int o  = idx & 63;
    int r  = idx >> 6;          // d*Cin + ci
    int ci = r % Cin;
    int d  = r / Cin;
    __nv_bfloat16 h, l; split_bf16(w[(size_t)(o * Cin + ci) * 9 + d], h, l);
    g_w1s[idx] = __nv_bfloat162(h, l);
}
__global__ void prep_w2_kernel(const float* __restrict__ w2)
{
    int idx = blockIdx.x * blockDim.x + threadIdx.x;   // over 8192
    if (idx >= 128 * 64) return;
    __nv_bfloat16 h, l; split_bf16(w2[idx], h, l);
    g_w2s[idx] = __nv_bfloat162(h, l);
}

// ---------------------------------------------------------------------------
// K1: conv3x3 SAME via wmma. Block = 64 oc x 16x16 pixel tile of one sample.
// 8 warps; warp owns 2 y-rows x all 64 oc. For each (dy,dx) tap the conv is
// a [x16 x ci16] @ [ci16 x oc16] GEMM on a shifted patch window.
// Patch [yy][xx][ci24] (lda=24 -> conflict-free ldmatrix); staged with xx
// innermost (coalesced global reads). Weights [d][ci16][oc72] direct from
// pre-split g_w1s. 3-term bf16 split: acc += Ah*Bh + Ah*Bl + Al*Bh.
// ---------------------------------------------------------------------------
#define CPAD 24
#define WPAD 72
__global__ __launch_bounds__(256) void conv3x3_wmma_kernel(
    const float* __restrict__ x, int Cin)
{
    extern __shared__ char dynsmem[];
    __nv_bfloat16* sPh = reinterpret_cast<__nv_bfloat16*>(dynsmem);   // [18][18][24]
    __nv_bfloat16* sPl = sPh + 18 * 18 * CPAD;
    __nv_bfloat16* sWh = sPl + 18 * 18 * CPAD;                        // [9][16][72]
    __nv_bfloat16* sWl = sWh + 9 * 16 * WPAD;

    const int b   = blockIdx.x;
    const int n   = b >> 8;             // 256 tiles per sample
    const int t   = b & 255;
    const int ty0 = (t >> 4) << 4;
    const int tx0 = (t & 15) << 4;
    const int tid = threadIdx.x;
    const int wid = tid >> 5;
    const int y0  = wid << 1;           // warp rows y0, y0+1

    wmma::fragment<wmma::accumulator, 16, 16, 16, float> acc[2][4];
#pragma unroll
    for (int y2 = 0; y2 < 2; y2++)
#pragma unroll
        for (int f = 0; f < 4; f++) wmma::fill_fragment(acc[y2][f], 0.f);

    const int nchunks = Cin >> 4;
    for (int cb = 0; cb < nchunks; cb++) {
        const int ci0 = cb << 4;
        __syncthreads();
        // stage patch [yy][xx][ci], xx innermost in idx => coalesced LDG
        for (int idx = tid; idx < 16 * 18 * 18; idx += 256) {
            int ci  = idx / 324;
            int rem = idx - ci * 324;
            int yy  = rem / 18;
            int xx  = rem - yy * 18;
            int gy = ty0 + yy - 1, gx = tx0 + xx - 1;
            float v = 0.f;
            if ((unsigned)gy < 256u && (unsigned)gx < 256u)
                v = x[(((size_t)(n * Cin + ci0 + ci)) << 16) + (gy << 8) + gx];
            __nv_bfloat16 h, l; split_bf16(v, h, l);
            sPh[rem * CPAD + ci] = h; sPl[rem * CPAD + ci] = l;
        }
        // stage weights [d][ci][oc] from pre-split table (coalesced 4B loads)
        for (int idx = tid; idx < 9 * 16 * 64; idx += 256) {
            int d  = idx >> 10;
            int r  = idx & 1023;
            int ci = r >> 6;
            int o  = r & 63;
            __nv_bfloat162 hl = g_w1s[(d * Cin + ci0 + ci) * 64 + o];
            sWh[(d * 16 + ci) * WPAD + o] = hl.x;
            sWl[(d * 16 + ci) * WPAD + o] = hl.y;
        }
        __syncthreads();

#pragma unroll 1
        for (int d = 0; d < 9; d++) {
            const int ky = d / 3, kx = d - 3 * (d / 3);
            wmma::fragment<wmma::matrix_b, 16, 16, 16, __nv_bfloat16, wmma::row_major> bh[4], bl[4];
#pragma unroll
            for (int f = 0; f < 4; f++) {
                wmma::load_matrix_sync(bh[f], sWh + d * 16 * WPAD + f * 16, WPAD);
                wmma::load_matrix_sync(bl[f], sWl + d * 16 * WPAD + f * 16, WPAD);
            }
#pragma unroll
            for (int y2 = 0; y2 < 2; y2++) {
                const int off = ((y0 + y2 + ky) * 18 + kx) * CPAD;
                wmma::fragment<wmma::matrix_a, 16, 16, 16, __nv_bfloat16, wmma::row_major> ah, al;
                wmma::load_matrix_sync(ah, sPh + off, CPAD);
                wmma::load_matrix_sync(al, sPl + off, CPAD);
#pragma unroll
                for (int f = 0; f < 4; f++) {
                    wmma::mma_sync(acc[y2][f], ah, bh[f], acc[y2][f]);
                    wmma::mma_sync(acc[y2][f], ah, bl[f], acc[y2][f]);
                    wmma::mma_sync(acc[y2][f], al, bh[f], acc[y2][f]);
                }
            }
        }
    }

    // store: frag (m=x, n=oc) -> y1[oc][y][x]  => mem_col_major, ldm=65536
#pragma unroll
    for (int y2 = 0; y2 < 2; y2++)
#pragma unroll
        for (int f = 0; f < 4; f++) {
            float* p = g_y1 + (((size_t)(n * 64 + f * 16)) << 16)
                     + ((ty0 + y0 + y2) << 8) + tx0;
            wmma::store_matrix_sync(p, acc[y2][f], 65536, wmma::mem_col_major);
        }
}

// ---------------------------------------------------------------------------
// K2/K5: per-row (65536 elems) sum / sumsq. which=0 -> y1, which=1 -> z.
// ---------------------------------------------------------------------------
__global__ __launch_bounds__(256) void rowstat_kernel(int which)
{
    const float* buf = which ? g_z : g_y1;
    float* stat      = which ? g_stat2 : g_stat1;
    const int row = blockIdx.x;
    const float4* p = reinterpret_cast<const float4*>(buf + ((size_t)row << 16));
    float s = 0.f, q = 0.f;
    for (int i = threadIdx.x; i < 16384; i += 256) {
        float4 v = p[i];
        s += v.x + v.y + v.z + v.w;
        q += v.x * v.x + v.y * v.y + v.z * v.z + v.w * v.w;
    }
    __shared__ float rs[256], rq[256];
    rs[threadIdx.x] = s; rq[threadIdx.x] = q;
    __syncthreads();
    for (int st = 128; st > 0; st >>= 1) {
        if (threadIdx.x < st) {
            rs[threadIdx.x] += rs[threadIdx.x + st];
            rq[threadIdx.x] += rq[threadIdx.x + st];
        }
        __syncthreads();
    }
    if (threadIdx.x == 0) { stat[row * 2] = rs[0]; stat[row * 2 + 1] = rq[0]; }
}

// ---------------------------------------------------------------------------
// K3/K6: BN coefficients. h = relu(a*x + b). pooled => batch stats (0,2,3).
// ---------------------------------------------------------------------------
__global__ void bncoef_kernel(const float* __restrict__ gamma,
                              const float* __restrict__ beta,
                              int C, int pooled, int which)
{
    int t = blockIdx.x * blockDim.x + threadIdx.x;
    if (t >= 5 * C) return;
    const float* stat = which ? g_stat2 : g_stat1;
    float* A = which ? g_a2 : g_a1;
    float* B = which ? g_b2 : g_b1;
    int o = t % C;
    float mean, var;
    if (pooled) {
        float s = 0.f, q = 0.f;
        for (int m = 0; m < 5; m++) {
            s += stat[(m * C + o) * 2];
            q += stat[(m * C + o) * 2 + 1];
        }
        const float inv = 1.f / (5.f * 65536.f);
        mean = s * inv; var = q * inv - mean * mean;
    } else {
        const float inv = 1.f / 65536.f;
        mean = stat[t * 2] * inv; var = stat[t * 2 + 1] * inv - mean * mean;
    }
    float a = gamma[o] * rsqrtf(var + 1e-5f);
    A[t] = a;
    B[t] = fmaf(-mean, a, beta[o]);
}

// ---------------------------------------------------------------------------
// K4: wmma GEMM. Block tile M=128 oc x N=128 px, K=64 (4 stages of 16).
// A from pre-split g_w2s, staged [128][72]. B = relu(bn1(y1)) split,
// staged [16][136] per k-stage. 8 warps as 4m x 2n.
// ---------------------------------------------------------------------------
#define APAD 72
#define BPAD 136
__global__ __launch_bounds__(256) void gemm_wmma_kernel()
{
    __shared__ __nv_bfloat16 sAh[128 * APAD];   // 18.0 KB
    __shared__ __nv_bfloat16 sAl[128 * APAD];   // 18.0 KB
    __shared__ __nv_bfloat16 sBh[16 * BPAD];    // 4.25 KB
    __shared__ __nv_bfloat16 sBl[16 * BPAD];    // 4.25 KB
    __shared__ float s_a[64], s_b[64];

    const int blk = blockIdx.x;
    const int n   = blk >> 9;            // 512 pixel tiles per sample
    const int p0  = (blk & 511) << 7;
    const int tid = threadIdx.x;
    const int wid = tid >> 5;
    const int warp_m = wid & 3;          // 32-oc slice
    const int warp_n = wid >> 2;         // 64-px slice

    if (tid < 64) { s_a[tid] = g_a1[n * 64 + tid]; s_b[tid] = g_b1[n * 64 + tid]; }

    // stage A from pre-split w2: [oc][k], ld=APAD (coalesced 4B loads)
    for (int idx = tid; idx < 128 * 64; idx += 256) {
        int oc = idx >> 6, k = idx & 63;
        __nv_bfloat162 hl = g_w2s[idx];
        sAh[oc * APAD + k] = hl.x; sAl[oc * APAD + k] = hl.y;
    }

    wmma::fragment<wmma::accumulator, 16, 16, 16, float> acc[2][4];
#pragma unroll
    for (int mi = 0; mi < 2; mi++)
#pragma unroll
        for (int j = 0; j < 4; j++) wmma::fill_fragment(acc[mi][j], 0.f);

    for (int ks = 0; ks < 4; ks++) {
        const int k0 = ks << 4;
        __syncthreads();
        // stage B: h = relu(a*y1+b) for k rows k0..k0+15, 128 px
        for (int idx = tid; idx < 16 * 32; idx += 256) {   // float4 granules
            int kk = idx >> 5;
            int p4 = (idx & 31) << 2;
            int o  = k0 + kk;
            float4 v = *reinterpret_cast<const float4*>(
                g_y1 + (((size_t)(n * 64 + o)) << 16) + p0 + p4);
            float a = s_a[o], bb = s_b[o];
            float hv[4] = { fmaxf(fmaf(a, v.x, bb), 0.f), fmaxf(fmaf(a, v.y, bb), 0.f),
                            fmaxf(fmaf(a, v.z, bb), 0.f), fmaxf(fmaf(a, v.w, bb), 0.f) };
#pragma unroll
            for (int q = 0; q < 4; q++) {
                __nv_bfloat16 h, l; split_bf16(hv[q], h, l);
                sBh[kk * BPAD + p4 + q] = h;
                sBl[kk * BPAD + p4 + q] = l;
            }
        }
        __syncthreads();

        wmma::fragment<wmma::matrix_a, 16, 16, 16, __nv_bfloat16, wmma::row_major> ah[2], al[2];
#pragma unroll
        for (int mi = 0; mi < 2; mi++) {
            const int oc = (warp_m << 5) + (mi << 4);
            wmma::load_matrix_sync(ah[mi], sAh + oc * APAD + k0, APAD);
            wmma::load_matrix_sync(al[mi], sAl + oc * APAD + k0, APAD);
        }
#pragma unroll
        for (int j = 0; j < 4; j++) {
            wmma::fragment<wmma::matrix_b, 16, 16, 16, __nv_bfloat16, wmma::row_major> bh, bl;
            const int px = (warp_n << 6) + (j << 4);
            wmma::load_matrix_sync(bh, sBh + px, BPAD);
            wmma::load_matrix_sync(bl, sBl + px, BPAD);
#pragma unroll
            for (int mi = 0; mi < 2; mi++) {
                wmma::mma_sync(acc[mi][j], ah[mi], bh, acc[mi][j]);
                wmma::mma_sync(acc[mi][j], ah[mi], bl, acc[mi][j]);
                wmma::mma_sync(acc[mi][j], al[mi], bh, acc[mi][j]);
            }
        }
    }

    // store: frag (m=oc, n=px) -> z[oc][px]  => mem_row_major, ldm=65536
#pragma unroll
    for (int mi = 0; mi < 2; mi++)
#pragma unroll
        for (int j = 0; j < 4; j++) {
            const int oc = (warp_m << 5) + (mi << 4);
            float* p = g_z + (((size_t)(n * 128 + oc)) << 16)
                     + p0 + (warp_n << 6) + (j << 4);
            wmma::store_matrix_sync(p, acc[mi][j], 65536, wmma::mem_row_major);
        }
}

// ---------------------------------------------------------------------------
// K7: feat[e][row] = mean_pix relu(a2*z + b2)   (row = n*128+oc)
// ---------------------------------------------------------------------------
__global__ __launch_bounds__(256) void feat_kernel(int e)
{
    const int row = blockIdx.x;   // 0..639
    const float a = g_a2[row], b = g_b2[row];
    const float4* p = reinterpret_cast<const float4*>(g_z + ((size_t)row << 16));
    float s = 0.f;
    for (int i = threadIdx.x; i < 16384; i += 256) {
        float4 v = p[i];
        s += fmaxf(fmaf(a, v.x, b), 0.f) + fmaxf(fmaf(a, v.y, b), 0.f)
           + fmaxf(fmaf(a, v.z, b), 0.f) + fmaxf(fmaf(a, v.w, b), 0.f);
    }
    __shared__ float rs[256];
    rs[threadIdx.x] = s;
    __syncthreads();
    for (int st = 128; st > 0; st >>= 1) {
        if (threadIdx.x < st) rs[threadIdx.x] += rs[threadIdx.x + st];
        __syncthreads();
    }
    if (threadIdx.x == 0) g_feat[e * 640 + row] = rs[0] * (1.f / 65536.f);
}

// ---------------------------------------------------------------------------
// K8: normalize features, similarity logits, masked logsumexp CE, weighted avg
// ---------------------------------------------------------------------------
__global__ void loss_kernel(const int* __restrict__ mask, float* __restrict__ out)
{
    __shared__ float Q[3][5][128];
    __shared__ float Kf[3][5][128];
    __shared__ float S[3][5][5];
    __shared__ float X[3][5][3];
    __shared__ int cnt[12];
    __shared__ float wls[15], wts[15];
    const int tid = threadIdx.x;

    if (tid < 30) {                       // normalize: 30 feature rows
        int path = tid / 15;
        int r = tid % 15;
        int g = r / 5, i = r % 5;
        const float* f = g_feat + ((path * 3 + g) * 5 + i) * 128;
        float nr = 0.f;
        for (int d = 0; d < 128; d++) nr += f[d] * f[d];
        float inv = 1.f / fmaxf(sqrtf(nr), 1e-12f);
        float* dst = path ? &Kf[g][i][0] : &Q[g][i][0];
        for (int d = 0; d < 128; d++) dst[d] = f[d] * inv;
    }
    if (tid < 12) cnt[tid] = 0;
    __syncthreads();

    // decision_mask counts: cnt[g][agent]
    for (int idx = tid; idx < 4 * 128 * 128; idx += blockDim.x) {
        int m = mask[idx];
        if (m >= 1) atomicAdd(&cnt[(m - 1) * 4 + (idx >> 14)], 1);
    }

    if (tid < 75) {                       // S[g,i,j] = Q[g,i].K[g,j]
        int g = tid / 25, i = (tid % 25) / 5, j = tid % 5;
        float s = 0.f;
        for (int d = 0; d < 128; d++) s += Q[g][i][d] * Kf[g][j][d];
        S[g][i][j] = s;
    } else if (tid < 120) {               // X[g,i,h] = Q[g,i].K[h,i]
        int r = tid - 75;
        int g = r / 15, i = (r % 15) / 3, h = r % 3;
        float s = 0.f;
        for (int d = 0; d < 128; d++) s += Q[g][i][d] * Kf[h][i][d];
        X[g][i][h] = s;
    }
    __syncthreads();

    if (tid < 15) {
        int g = tid / 5, i = tid % 5;
        float lg[9];
        lg[0] = S[g][i][i];
        for (int j = 0; j < 5; j++) lg[1 + j] = (j == i) ? -1e9f : S[g][i][j];
        for (int h = 0; h < 3; h++) lg[6 + h] = (h == g) ? -1e9f : X[g][i][h];
        float mx = -3.4e38f;
        for (int r = 0; r < 9; r++) { lg[r] *= 10.f; mx = fmaxf(mx, lg[r]); }  // /TEMP
        float se = 0.f;
        for (int r = 0; r < 9; r++) se += expf(lg[r] - mx);
        float lse = mx + logf(se);
        float lt = lse - lg[0];
        float wgt = (i == 0) ? 0.f : (float)cnt[g * 4 + i - 1];
        wls[tid] = wgt * lt;
        wts[tid] = wgt;
    }
    __syncthreads();
    if (tid == 0) {
        float ws = 0.f, tot = 0.f;
        for (int r = 0; r < 15; r++) { ws += wls[r]; tot += wts[r]; }
        out[0] = (tot > 0.f) ? (ws / fmaxf(tot, 1.f)) : 0.f;
    }
}

// ---------------------------------------------------------------------------
extern "C" void kernel_launch(void* const* d_in, const int* in_sizes, int n_in,
                              void* d_out, int out_size)
{
    (void)in_sizes; (void)n_in; (void)out_size;
    const int CONV_SMEM = (2 * 18 * 18 * CPAD + 2 * 9 * 16 * WPAD) * 2;  // 72576 B
    static int attr_done = 0;
    if (!attr_done) {
        cudaFuncSetAttribute(conv3x3_wmma_kernel,
                             cudaFuncAttributeMaxDynamicSharedMemorySize, CONV_SMEM);
        attr_done = 1;
    }

    const int Cin[3] = {64, 32, 16};
    for (int g = 0; g < 3; g++) {
        const float* w1 = (const float*)d_in[g * 8 + 2];
        const float* g1 = (const float*)d_in[g * 8 + 3];
        const float* b1 = (const float*)d_in[g * 8 + 4];
        const float* w2 = (const float*)d_in[g * 8 + 5];
        const float* g2 = (const float*)d_in[g * 8 + 6];
        const float* b2 = (const float*)d_in[g * 8 + 7];

        prep_w1_kernel<<<(9 * Cin[g] * 64 + 255) / 256, 256>>>(w1, Cin[g]);
        prep_w2_kernel<<<32, 256>>>(w2);

        for (int path = 0; path < 2; path++) {
            const float* x = (const float*)d_in[g * 8 + path];   // 0:sparse 1:dense

            conv3x3_wmma_kernel<<<1280, 256, CONV_SMEM>>>(x, Cin[g]);
            rowstat_kernel<<<320, 256>>>(0);
            bncoef_kernel<<<2, 256>>>(g1, b1, 64, path, 0);
            gemm_wmma_kernel<<<2560, 256>>>();
            rowstat_kernel<<<640, 256>>>(1);
            bncoef_kernel<<<3, 256>>>(g2, b2, 128, path, 1);
            feat_kernel<<<640, 256>>>(path * 3 + g);
        }
    }
    loss_kernel<<<1, 256>>>((const int*)d_in[24], (float*)d_out);
}

// round 15
// speedup vs baseline: 1.0818x; 1.0818x over previous
#include <cuda_runtime.h>
#include <cuda_bf16.h>
#include <mma.h>
#include <cstdint>

using namespace nvcuda;

// ---------------------------------------------------------------------------
// ContrastiveSparsityLoss — wmma bf16-split conv + GEMM, fused BN stats,
// bf16 z scratch. R15: kill the scratch-traffic ledger (rowstat passes gone,
// z halved), stats computed exactly from fp32 accumulators in epilogues.
// ---------------------------------------------------------------------------

__device__ float g_y1[5 * 64 * 65536];            // 83.9 MB fp32
__device__ __nv_bfloat16 g_zb[5 * 128 * 65536];   // 83.9 MB bf16
__device__ float g_stat1[5 * 64 * 2];
__device__ float g_stat2[5 * 128 * 2];
__device__ float g_a1[5 * 64];
__device__ float g_b1[5 * 64];
__device__ float g_a2[5 * 128];
__device__ float g_b2[5 * 128];
__device__ float g_feat[6 * 5 * 128];             // [e][n][oc]
__device__ __nv_bfloat162 g_w1s[9 * 64 * 64];     // [d][ci][oc] (hi,lo)
__device__ __nv_bfloat162 g_w2s[128 * 64];        // [oc][k]     (hi,lo)

__device__ __forceinline__ void split_bf16(float v, __nv_bfloat16& hi, __nv_bfloat16& lo) {
    hi = __float2bfloat16(v);
    lo = __float2bfloat16(v - __bfloat162float(hi));
}

// ---------------------------------------------------------------------------
__global__ void zero_stats_kernel()
{
    int t = threadIdx.x;
    for (int i = t; i < 640; i += 256)  g_stat1[i] = 0.f;
    for (int i = t; i < 1280; i += 256) g_stat2[i] = 0.f;
}

// prep: pre-split weights (once per granularity).
__global__ void prep_w1_kernel(const float* __restrict__ w, int Cin)
{
    int idx = blockIdx.x * blockDim.x + threadIdx.x;   // over 9*Cin*64
    if (idx >= 9 * Cin * 64) return;
    int o  = idx & 63;
    int r  = idx >> 6;          // d*Cin + ci
    int ci = r % Cin;
    int d  = r / Cin;
    __nv_bfloat16 h, l; split_bf16(w[(size_t)(o * Cin + ci) * 9 + d], h, l);
    g_w1s[idx] = __nv_bfloat162(h, l);
}
__global__ void prep_w2_kernel(const float* __restrict__ w2)
{
    int idx = blockIdx.x * blockDim.x + threadIdx.x;   // over 8192
    if (idx >= 128 * 64) return;
    __nv_bfloat16 h, l; split_bf16(w2[idx], h, l);
    g_w2s[idx] = __nv_bfloat162(h, l);
}

// ---------------------------------------------------------------------------
// K1: conv3x3 SAME via wmma. Block = 64 oc x 16x16 pixels. Epilogue: frags ->
// smem (fp32), exact sum/sumsq per oc -> atomicAdd g_stat1, y1 via float4.
// ---------------------------------------------------------------------------
#define CPAD 24
#define WPAD 72
__global__ __launch_bounds__(256) void conv3x3_wmma_kernel(
    const float* __restrict__ x, int Cin)
{
    extern __shared__ char dynsmem[];
    __nv_bfloat16* sPh = reinterpret_cast<__nv_bfloat16*>(dynsmem);   // [18*18][24]
    __nv_bfloat16* sPl = sPh + 18 * 18 * CPAD;
    __nv_bfloat16* sWh = sPl + 18 * 18 * CPAD;                        // [9*16][72]
    __nv_bfloat16* sWl = sWh + 9 * 16 * WPAD;

    const int b   = blockIdx.x;
    const int n   = b >> 8;
    const int t   = b & 255;
    const int ty0 = (t >> 4) << 4;
    const int tx0 = (t & 15) << 4;
    const int tid = threadIdx.x;
    const int wid = tid >> 5;
    const int lane = tid & 31;
    const int y0  = wid << 1;

    wmma::fragment<wmma::accumulator, 16, 16, 16, float> acc[2][4];
#pragma unroll
    for (int y2 = 0; y2 < 2; y2++)
#pragma unroll
        for (int f = 0; f < 4; f++) wmma::fill_fragment(acc[y2][f], 0.f);

    const int nchunks = Cin >> 4;
    for (int cb = 0; cb < nchunks; cb++) {
        const int ci0 = cb << 4;
        __syncthreads();
        // stage patch [yy*18+xx][ci], xx innermost => coalesced LDG
        for (int idx = tid; idx < 16 * 18 * 18; idx += 256) {
            int ci  = idx / 324;
            int rem = idx - ci * 324;
            int yy  = rem / 18;
            int xx  = rem - yy * 18;
            int gy = ty0 + yy - 1, gx = tx0 + xx - 1;
            float v = 0.f;
            if ((unsigned)gy < 256u && (unsigned)gx < 256u)
                v = x[(((size_t)(n * Cin + ci0 + ci)) << 16) + (gy << 8) + gx];
            __nv_bfloat16 h, l; split_bf16(v, h, l);
            sPh[rem * CPAD + ci] = h; sPl[rem * CPAD + ci] = l;
        }
        // stage weights [d*16+ci][oc] packed pairs (4B STS)
        for (int idx = tid; idx < 9 * 16 * 32; idx += 256) {
            int d   = idx >> 9;          // /512
            int rem = idx & 511;
            int ci  = rem >> 5;
            int o2  = (rem & 31) << 1;
            __nv_bfloat162 h0 = g_w1s[(d * Cin + ci0 + ci) * 64 + o2];
            __nv_bfloat162 h1 = g_w1s[(d * Cin + ci0 + ci) * 64 + o2 + 1];
            *reinterpret_cast<__nv_bfloat162*>(&sWh[(d * 16 + ci) * WPAD + o2])
                = __nv_bfloat162(h0.x, h1.x);
            *reinterpret_cast<__nv_bfloat162*>(&sWl[(d * 16 + ci) * WPAD + o2])
                = __nv_bfloat162(h0.y, h1.y);
        }
        __syncthreads();

#pragma unroll 1
        for (int d = 0; d < 9; d++) {
            const int ky = d / 3, kx = d - 3 * (d / 3);
            wmma::fragment<wmma::matrix_b, 16, 16, 16, __nv_bfloat16, wmma::row_major> bh[4], bl[4];
#pragma unroll
            for (int f = 0; f < 4; f++) {
                wmma::load_matrix_sync(bh[f], sWh + d * 16 * WPAD + f * 16, WPAD);
                wmma::load_matrix_sync(bl[f], sWl + d * 16 * WPAD + f * 16, WPAD);
            }
#pragma unroll
            for (int y2 = 0; y2 < 2; y2++) {
                const int off = ((y0 + y2 + ky) * 18 + kx) * CPAD;
                wmma::fragment<wmma::matrix_a, 16, 16, 16, __nv_bfloat16, wmma::row_major> ah, al;
                wmma::load_matrix_sync(ah, sPh + off, CPAD);
                wmma::load_matrix_sync(al, sPl + off, CPAD);
#pragma unroll
                for (int f = 0; f < 4; f++) {
                    wmma::mma_sync(acc[y2][f], ah, bh[f], acc[y2][f]);
                    wmma::mma_sync(acc[y2][f], ah, bl[f], acc[y2][f]);
                    wmma::mma_sync(acc[y2][f], al, bh[f], acc[y2][f]);
                }
            }
        }
    }

    // epilogue: frags -> smem fp32 [oc64][y16*x16], stats + coalesced y1 write
    __syncthreads();                       // all warps done reading patch smem
    float* sY = reinterpret_cast<float*>(dynsmem);   // 64 KB, aliases patch
#pragma unroll
    for (int y2 = 0; y2 < 2; y2++)
#pragma unroll
        for (int f = 0; f < 4; f++)        // element(x, ocl) -> ptr[ocl*256 + x]
            wmma::store_matrix_sync(sY + f * 16 * 256 + (y0 + y2) * 16,
                                    acc[y2][f], 256, wmma::mem_col_major);
    __syncthreads();

    // stats: warp w owns oc rows 8w..8w+7 (256 px each)
#pragma unroll
    for (int u = 0; u < 8; u++) {
        const int oc = (wid << 3) + u;
        float s = 0.f, q = 0.f;
#pragma unroll
        for (int i = 0; i < 8; i++) {
            float v = sY[oc * 256 + lane + (i << 5)];
            s += v; q += v * v;
        }
#pragma unroll
        for (int off = 16; off > 0; off >>= 1) {
            s += __shfl_down_sync(0xffffffffu, s, off);
            q += __shfl_down_sync(0xffffffffu, q, off);
        }
        if (lane == 0) {
            atomicAdd(&g_stat1[((n << 6) + oc) * 2],     s);
            atomicAdd(&g_stat1[((n << 6) + oc) * 2 + 1], q);
        }
    }
    // y1 write, float4
    for (int idx = tid; idx < 4096; idx += 256) {
        int oc = idx >> 6;
        int r  = idx & 63;
        int y  = r >> 2;
        int xq = r & 3;
        float4 v = reinterpret_cast<float4*>(sY)[idx];
        *reinterpret_cast<float4*>(
            g_y1 + (((size_t)((n << 6) + oc)) << 16) + ((ty0 + y) << 8) + tx0 + (xq << 2)) = v;
    }
}

// ---------------------------------------------------------------------------
// K3/K6: BN coefficients. h = relu(a*x + b). pooled => batch stats (0,2,3).
// ---------------------------------------------------------------------------
__global__ void bncoef_kernel(const float* __restrict__ gamma,
                              const float* __restrict__ beta,
                              int C, int pooled, int which)
{
    int t = blockIdx.x * blockDim.x + threadIdx.x;
    if (t >= 5 * C) return;
    const float* stat = which ? g_stat2 : g_stat1;
    float* A = which ? g_a2 : g_a1;
    float* B = which ? g_b2 : g_b1;
    int o = t % C;
    float mean, var;
    if (pooled) {
        float s = 0.f, q = 0.f;
        for (int m = 0; m < 5; m++) {
            s += stat[(m * C + o) * 2];
            q += stat[(m * C + o) * 2 + 1];
        }
        const float inv = 1.f / (5.f * 65536.f);
        mean = s * inv; var = q * inv - mean * mean;
    } else {
        const float inv = 1.f / 65536.f;
        mean = stat[t * 2] * inv; var = stat[t * 2 + 1] * inv - mean * mean;
    }
    float a = gamma[o] * rsqrtf(var + 1e-5f);
    A[t] = a;
    B[t] = fmaf(-mean, a, beta[o]);
}

// ---------------------------------------------------------------------------
// K4: wmma GEMM, M=128 oc x N=128 px, K=64. Epilogue: per-frag smem scratch,
// exact stats from fp32 accs -> atomicAdd g_stat2, z written as bf16 (uint4).
// ---------------------------------------------------------------------------
#define APAD 72
#define BPAD 136
#define SCRW 20
__global__ __launch_bounds__(256) void gemm_wmma_kernel()
{
    extern __shared__ char gsmem[];
    __nv_bfloat16* sAh = reinterpret_cast<__nv_bfloat16*>(gsmem);       // 128*72
    __nv_bfloat16* sAl = sAh + 128 * APAD;
    __nv_bfloat16* sBh = sAl + 128 * APAD;                               // 16*136
    __nv_bfloat16* sBl = sBh + 16 * BPAD;
    float* s_a = reinterpret_cast<float*>(sBl + 16 * BPAD);
    float* s_b = s_a + 64;
    float* sScr = s_b + 64;                                              // 8*16*20

    const int blk = blockIdx.x;
    const int n   = blk >> 9;
    const int p0  = (blk & 511) << 7;
    const int tid = threadIdx.x;
    const int wid = tid >> 5;
    const int lane = tid & 31;
    const int warp_m = wid & 3;
    const int warp_n = wid >> 2;

    if (tid < 64) { s_a[tid] = g_a1[n * 64 + tid]; s_b[tid] = g_b1[n * 64 + tid]; }

    // stage A from pre-split w2, packed pair stores
    for (int idx = tid; idx < 128 * 32; idx += 256) {
        int oc = idx >> 5;
        int k2 = (idx & 31) << 1;
        __nv_bfloat162 a0 = g_w2s[oc * 64 + k2];
        __nv_bfloat162 a1 = g_w2s[oc * 64 + k2 + 1];
        *reinterpret_cast<__nv_bfloat162*>(&sAh[oc * APAD + k2]) = __nv_bfloat162(a0.x, a1.x);
        *reinterpret_cast<__nv_bfloat162*>(&sAl[oc * APAD + k2]) = __nv_bfloat162(a0.y, a1.y);
    }

    wmma::fragment<wmma::accumulator, 16, 16, 16, float> acc[2][4];
#pragma unroll
    for (int mi = 0; mi < 2; mi++)
#pragma unroll
        for (int j = 0; j < 4; j++) wmma::fill_fragment(acc[mi][j], 0.f);

    for (int ks = 0; ks < 4; ks++) {
        const int k0 = ks << 4;
        __syncthreads();
        for (int idx = tid; idx < 16 * 32; idx += 256) {
            int kk = idx >> 5;
            int p4 = (idx & 31) << 2;
            int o  = k0 + kk;
            float4 v = *reinterpret_cast<const float4*>(
                g_y1 + (((size_t)(n * 64 + o)) << 16) + p0 + p4);
            float a = s_a[o], bb = s_b[o];
            float hv[4] = { fmaxf(fmaf(a, v.x, bb), 0.f), fmaxf(fmaf(a, v.y, bb), 0.f),
                            fmaxf(fmaf(a, v.z, bb), 0.f), fmaxf(fmaf(a, v.w, bb), 0.f) };
            __nv_bfloat16 h0, l0, h1, l1;
            split_bf16(hv[0], h0, l0); split_bf16(hv[1], h1, l1);
            *reinterpret_cast<__nv_bfloat162*>(&sBh[kk * BPAD + p4]) = __nv_bfloat162(h0, h1);
            *reinterpret_cast<__nv_bfloat162*>(&sBl[kk * BPAD + p4]) = __nv_bfloat162(l0, l1);
            split_bf16(hv[2], h0, l0); split_bf16(hv[3], h1, l1);
            *reinterpret_cast<__nv_bfloat162*>(&sBh[kk * BPAD + p4 + 2]) = __nv_bfloat162(h0, h1);
            *reinterpret_cast<__nv_bfloat162*>(&sBl[kk * BPAD + p4 + 2]) = __nv_bfloat162(l0, l1);
        }
        __syncthreads();

        wmma::fragment<wmma::matrix_a, 16, 16, 16, __nv_bfloat16, wmma::row_major> ah[2], al[2];
#pragma unroll
        for (int mi = 0; mi < 2; mi++) {
            const int oc = (warp_m << 5) + (mi << 4);
            wmma::load_matrix_sync(ah[mi], sAh + oc * APAD + k0, APAD);
            wmma::load_matrix_sync(al[mi], sAl + oc * APAD + k0, APAD);
        }
#pragma unroll
        for (int j = 0; j < 4; j++) {
            wmma::fragment<wmma::matrix_b, 16, 16, 16, __nv_bfloat16, wmma::row_major> bh, bl;
            const int px = (warp_n << 6) + (j << 4);
            wmma::load_matrix_sync(bh, sBh + px, BPAD);
            wmma::load_matrix_sync(bl, sBl + px, BPAD);
#pragma unroll
            for (int mi = 0; mi < 2; mi++) {
                wmma::mma_sync(acc[mi][j], ah[mi], bh, acc[mi][j]);
                wmma::mma_sync(acc[mi][j], ah[mi], bl, acc[mi][j]);
                wmma::mma_sync(acc[mi][j], al[mi], bh, acc[mi][j]);
            }
        }
    }

    // epilogue: per-warp scratch, stats + bf16 z
    float* scr = sScr + wid * 16 * SCRW;
    const int ocl = lane >> 1;
    const int half = lane & 1;
#pragma unroll
    for (int mi = 0; mi < 2; mi++) {
        const int oc = (warp_m << 5) + (mi << 4) + ocl;
        float s = 0.f, q = 0.f;
#pragma unroll
        for (int j = 0; j < 4; j++) {
            wmma::store_matrix_sync(scr, acc[mi][j], SCRW, wmma::mem_row_major);
            __syncwarp();
            uint4 u;
            uint32_t* uw = reinterpret_cast<uint32_t*>(&u);
#pragma unroll
            for (int i = 0; i < 4; i++) {
                float v0 = scr[ocl * SCRW + (half << 3) + (i << 1)];
                float v1 = scr[ocl * SCRW + (half << 3) + (i << 1) + 1];
                s += v0 + v1; q += v0 * v0 + v1 * v1;
                __nv_bfloat162 pk(__float2bfloat16(v0), __float2bfloat16(v1));
                uw[i] = *reinterpret_cast<uint32_t*>(&pk);
            }
            *reinterpret_cast<uint4*>(
                g_zb + (((size_t)(n * 128 + oc)) << 16)
                     + p0 + (warp_n << 6) + (j << 4) + (half << 3)) = u;
            __syncwarp();
        }
        s += __shfl_xor_sync(0xffffffffu, s, 1);
        q += __shfl_xor_sync(0xffffffffu, q, 1);
        if (half == 0) {
            atomicAdd(&g_stat2[(n * 128 + oc) * 2],     s);
            atomicAdd(&g_stat2[(n * 128 + oc) * 2 + 1], q);
        }
    }
}

// ---------------------------------------------------------------------------
// K7: feat[e][row] = mean_pix relu(a2*z + b2), z in bf16
// ---------------------------------------------------------------------------
__global__ __launch_bounds__(256) void feat_kernel(int e)
{
    const int row = blockIdx.x;   // 0..639
    const float a = g_a2[row], b = g_b2[row];
    const __nv_bfloat162* p = reinterpret_cast<const __nv_bfloat162*>(g_zb + ((size_t)row << 16));
    float s = 0.f;
    for (int i = threadIdx.x; i < 32768; i += 256) {
        float2 v = __bfloat1622float2(p[i]);
        s += fmaxf(fmaf(a, v.x, b), 0.f) + fmaxf(fmaf(a, v.y, b), 0.f);
    }
    __shared__ float rs[256];
    rs[threadIdx.x] = s;
    __syncthreads();
    for (int st = 128; st > 0; st >>= 1) {
        if (threadIdx.x < st) rs[threadIdx.x] += rs[threadIdx.x + st];
        __syncthreads();
    }
    if (threadIdx.x == 0) g_feat[e * 640 + row] = rs[0] * (1.f / 65536.f);
}

// ---------------------------------------------------------------------------
// K8: normalize features, similarity logits, masked logsumexp CE, weighted avg
// ---------------------------------------------------------------------------
__global__ void loss_kernel(const int* __restrict__ mask, float* __restrict__ out)
{
    __shared__ float Q[3][5][128];
    __shared__ float Kf[3][5][128];
    __shared__ float S[3][5][5];
    __shared__ float X[3][5][3];
    __shared__ int cnt[12];
    __shared__ float wls[15], wts[15];
    const int tid = threadIdx.x;

    if (tid < 30) {
        int path = tid / 15;
        int r = tid % 15;
        int g = r / 5, i = r % 5;
        const float* f = g_feat + ((path * 3 + g) * 5 + i) * 128;
        float nr = 0.f;
        for (int d = 0; d < 128; d++) nr += f[d] * f[d];
        float inv = 1.f / fmaxf(sqrtf(nr), 1e-12f);
        float* dst = path ? &Kf[g][i][0] : &Q[g][i][0];
        for (int d = 0; d < 128; d++) dst[d] = f[d] * inv;
    }
    if (tid < 12) cnt[tid] = 0;
    __syncthreads();

    for (int idx = tid; idx < 4 * 128 * 128; idx += blockDim.x) {
        int m = mask[idx];
        if (m >= 1) atomicAdd(&cnt[(m - 1) * 4 + (idx >> 14)], 1);
    }

    if (tid < 75) {
        int g = tid / 25, i = (tid % 25) / 5, j = tid % 5;
        float s = 0.f;
        for (int d = 0; d < 128; d++) s += Q[g][i][d] * Kf[g][j][d];
        S[g][i][j] = s;
    } else if (tid < 120) {
        int r = tid - 75;
        int g = r / 15, i = (r % 15) / 3, h = r % 3;
        float s = 0.f;
        for (int d = 0; d < 128; d++) s += Q[g][i][d] * Kf[h][i][d];
        X[g][i][h] = s;
    }
    __syncthreads();

    if (tid < 15) {
        int g = tid / 5, i = tid % 5;
        float lg[9];
        lg[0] = S[g][i][i];
        for (int j = 0; j < 5; j++) lg[1 + j] = (j == i) ? -1e9f : S[g][i][j];
        for (int h = 0; h < 3; h++) lg[6 + h] = (h == g) ? -1e9f : X[g][i][h];
        float mx = -3.4e38f;
        for (int r = 0; r < 9; r++) { lg[r] *= 10.f; mx = fmaxf(mx, lg[r]); }
        float se = 0.f;
        for (int r = 0; r < 9; r++) se += expf(lg[r] - mx);
        float lse = mx + logf(se);
        float lt = lse - lg[0];
        float wgt = (i == 0) ? 0.f : (float)cnt[g * 4 + i - 1];
        wls[tid] = wgt * lt;
        wts[tid] = wgt;
    }
    __syncthreads();
    if (tid == 0) {
        float ws = 0.f, tot = 0.f;
        for (int r = 0; r < 15; r++) { ws += wls[r]; tot += wts[r]; }
        out[0] = (tot > 0.f) ? (ws / fmaxf(tot, 1.f)) : 0.f;
    }
}

// ---------------------------------------------------------------------------
extern "C" void kernel_launch(void* const* d_in, const int* in_sizes, int n_in,
                              void* d_out, int out_size)
{
    (void)in_sizes; (void)n_in; (void)out_size;
    const int CONV_SMEM = (2 * 18 * 18 * CPAD + 2 * 9 * 16 * WPAD) * 2;  // 72576 B
    const int GEMM_SMEM = (2 * 128 * APAD + 2 * 16 * BPAD) * 2
                        + 128 * 4 + 8 * 16 * SCRW * 4;                   // 56320 B
    static int attr_done = 0;
    if (!attr_done) {
        cudaFuncSetAttribute(conv3x3_wmma_kernel,
                             cudaFuncAttributeMaxDynamicSharedMemorySize, CONV_SMEM);
        cudaFuncSetAttribute(gemm_wmma_kernel,
                             cudaFuncAttributeMaxDynamicSharedMemorySize, GEMM_SMEM);
        attr_done = 1;
    }

    const int Cin[3] = {64, 32, 16};
    for (int g = 0; g < 3; g++) {
        const float* w1 = (const float*)d_in[g * 8 + 2];
        const float* g1 = (const float*)d_in[g * 8 + 3];
        const float* b1 = (const float*)d_in[g * 8 + 4];
        const float* w2 = (const float*)d_in[g * 8 + 5];
        const float* g2 = (const float*)d_in[g * 8 + 6];
        const float* b2 = (const float*)d_in[g * 8 + 7];

        prep_w1_kernel<<<(9 * Cin[g] * 64 + 255) / 256, 256>>>(w1, Cin[g]);
        prep_w2_kernel<<<32, 256>>>(w2);

        for (int path = 0; path < 2; path++) {
            const float* x = (const float*)d_in[g * 8 + path];

            zero_stats_kernel<<<1, 256>>>();
            conv3x3_wmma_kernel<<<1280, 256, CONV_SMEM>>>(x, Cin[g]);
            bncoef_kernel<<<2, 256>>>(g1, b1, 64, path, 0);
            gemm_wmma_kernel<<<2560, 256, GEMM_SMEM>>>();
            bncoef_kernel<<<3, 256>>>(g2, b2, 128, path, 1);
            feat_kernel<<<640, 256>>>(path * 3 + g);
        }
    }
    loss_kernel<<<1, 256>>>((const int*)d_in[24], (float*)d_out);
}

// round 16
// speedup vs baseline: 1.2983x; 1.2002x over previous
#include <cuda_runtime.h>
#include <cuda_bf16.h>
#include <mma.h>
#include <cstdint>

using namespace nvcuda;

// ---------------------------------------------------------------------------
// ContrastiveSparsityLoss — wmma bf16-split conv + GEMM, fused BN stats,
// bf16 z scratch. R16: conv __launch_bounds__(256,2) -> 2 CTAs/SM (was
// register-capped at 1 CTA, occ 12.5%, tensor 28% — pure latency bind).
// ---------------------------------------------------------------------------

__device__ float g_y1[5 * 64 * 65536];            // 83.9 MB fp32
__device__ __nv_bfloat16 g_zb[5 * 128 * 65536];   // 83.9 MB bf16
__device__ float g_stat1[5 * 64 * 2];
__device__ float g_stat2[5 * 128 * 2];
__device__ float g_a1[5 * 64];
__device__ float g_b1[5 * 64];
__device__ float g_a2[5 * 128];
__device__ float g_b2[5 * 128];
__device__ float g_feat[6 * 5 * 128];             // [e][n][oc]
__device__ __nv_bfloat162 g_w1s[9 * 64 * 64];     // [d][ci][oc] (hi,lo)
__device__ __nv_bfloat162 g_w2s[128 * 64];        // [oc][k]     (hi,lo)

__device__ __forceinline__ void split_bf16(float v, __nv_bfloat16& hi, __nv_bfloat16& lo) {
    hi = __float2bfloat16(v);
    lo = __float2bfloat16(v - __bfloat162float(hi));
}

// ---------------------------------------------------------------------------
__global__ void zero_stats_kernel()
{
    int t = threadIdx.x;
    for (int i = t; i < 640; i += 256)  g_stat1[i] = 0.f;
    for (int i = t; i < 1280; i += 256) g_stat2[i] = 0.f;
}

// prep: pre-split weights (once per granularity).
__global__ void prep_w1_kernel(const float* __restrict__ w, int Cin)
{
    int idx = blockIdx.x * blockDim.x + threadIdx.x;   // over 9*Cin*64
    if (idx >= 9 * Cin * 64) return;
    int o  = idx & 63;
    int r  = idx >> 6;          // d*Cin + ci
    int ci = r % Cin;
    int d  = r / Cin;
    __nv_bfloat16 h, l; split_bf16(w[(size_t)(o * Cin + ci) * 9 + d], h, l);
    g_w1s[idx] = __nv_bfloat162(h, l);
}
__global__ void prep_w2_kernel(const float* __restrict__ w2)
{
    int idx = blockIdx.x * blockDim.x + threadIdx.x;   // over 8192
    if (idx >= 128 * 64) return;
    __nv_bfloat16 h, l; split_bf16(w2[idx], h, l);
    g_w2s[idx] = __nv_bfloat162(h, l);
}

// ---------------------------------------------------------------------------
// K1: conv3x3 SAME via wmma. Block = 64 oc x 16x16 pixels, 2 CTAs/SM.
// Epilogue: frags -> smem (fp32), exact stats -> atomicAdd, y1 via float4.
// ---------------------------------------------------------------------------
#define CPAD 24
#define WPAD 72
__global__ __launch_bounds__(256, 2) void conv3x3_wmma_kernel(
    const float* __restrict__ x, int Cin)
{
    extern __shared__ char dynsmem[];
    __nv_bfloat16* sPh = reinterpret_cast<__nv_bfloat16*>(dynsmem);   // [18*18][24]
    __nv_bfloat16* sPl = sPh + 18 * 18 * CPAD;
    __nv_bfloat16* sWh = sPl + 18 * 18 * CPAD;                        // [9*16][72]
    __nv_bfloat16* sWl = sWh + 9 * 16 * WPAD;

    const int b   = blockIdx.x;
    const int n   = b >> 8;
    const int t   = b & 255;
    const int ty0 = (t >> 4) << 4;
    const int tx0 = (t & 15) << 4;
    const int tid = threadIdx.x;
    const int wid = tid >> 5;
    const int lane = tid & 31;
    const int y0  = wid << 1;

    wmma::fragment<wmma::accumulator, 16, 16, 16, float> acc[2][4];
#pragma unroll
    for (int y2 = 0; y2 < 2; y2++)
#pragma unroll
        for (int f = 0; f < 4; f++) wmma::fill_fragment(acc[y2][f], 0.f);

    const int nchunks = Cin >> 4;
    for (int cb = 0; cb < nchunks; cb++) {
        const int ci0 = cb << 4;
        __syncthreads();
        // stage patch [yy*18+xx][ci], xx innermost => coalesced LDG
        for (int idx = tid; idx < 16 * 18 * 18; idx += 256) {
            int ci  = idx / 324;
            int rem = idx - ci * 324;
            int yy  = rem / 18;
            int xx  = rem - yy * 18;
            int gy = ty0 + yy - 1, gx = tx0 + xx - 1;
            float v = 0.f;
            if ((unsigned)gy < 256u && (unsigned)gx < 256u)
                v = x[(((size_t)(n * Cin + ci0 + ci)) << 16) + (gy << 8) + gx];
            __nv_bfloat16 h, l; split_bf16(v, h, l);
            sPh[rem * CPAD + ci] = h; sPl[rem * CPAD + ci] = l;
        }
        // stage weights [d*16+ci][oc] packed pairs (4B STS)
        for (int idx = tid; idx < 9 * 16 * 32; idx += 256) {
            int d   = idx >> 9;          // /512
            int rem = idx & 511;
            int ci  = rem >> 5;
            int o2  = (rem & 31) << 1;
            __nv_bfloat162 h0 = g_w1s[(d * Cin + ci0 + ci) * 64 + o2];
            __nv_bfloat162 h1 = g_w1s[(d * Cin + ci0 + ci) * 64 + o2 + 1];
            *reinterpret_cast<__nv_bfloat162*>(&sWh[(d * 16 + ci) * WPAD + o2])
                = __nv_bfloat162(h0.x, h1.x);
            *reinterpret_cast<__nv_bfloat162*>(&sWl[(d * 16 + ci) * WPAD + o2])
                = __nv_bfloat162(h0.y, h1.y);
        }
        __syncthreads();

#pragma unroll 1
        for (int d = 0; d < 9; d++) {
            const int ky = d / 3, kx = d - 3 * (d / 3);
            wmma::fragment<wmma::matrix_b, 16, 16, 16, __nv_bfloat16, wmma::row_major> bh[4], bl[4];
#pragma unroll
            for (int f = 0; f < 4; f++) {
                wmma::load_matrix_sync(bh[f], sWh + d * 16 * WPAD + f * 16, WPAD);
                wmma::load_matrix_sync(bl[f], sWl + d * 16 * WPAD + f * 16, WPAD);
            }
#pragma unroll
            for (int y2 = 0; y2 < 2; y2++) {
                const int off = ((y0 + y2 + ky) * 18 + kx) * CPAD;
                wmma::fragment<wmma::matrix_a, 16, 16, 16, __nv_bfloat16, wmma::row_major> ah, al;
                wmma::load_matrix_sync(ah, sPh + off, CPAD);
                wmma::load_matrix_sync(al, sPl + off, CPAD);
#pragma unroll
                for (int f = 0; f < 4; f++) {
                    wmma::mma_sync(acc[y2][f], ah, bh[f], acc[y2][f]);
                    wmma::mma_sync(acc[y2][f], ah, bl[f], acc[y2][f]);
                    wmma::mma_sync(acc[y2][f], al, bh[f], acc[y2][f]);
                }
            }
        }
    }

    // epilogue: frags -> smem fp32 [oc64][y16*x16], stats + coalesced y1 write
    __syncthreads();
    float* sY = reinterpret_cast<float*>(dynsmem);   // 64 KB, aliases patch
#pragma unroll
    for (int y2 = 0; y2 < 2; y2++)
#pragma unroll
        for (int f = 0; f < 4; f++)        // element(x, ocl) -> ptr[ocl*256 + x]
            wmma::store_matrix_sync(sY + f * 16 * 256 + (y0 + y2) * 16,
                                    acc[y2][f], 256, wmma::mem_col_major);
    __syncthreads();

    // stats: warp w owns oc rows 8w..8w+7 (256 px each)
#pragma unroll
    for (int u = 0; u < 8; u++) {
        const int oc = (wid << 3) + u;
        float s = 0.f, q = 0.f;
#pragma unroll
        for (int i = 0; i < 8; i++) {
            float v = sY[oc * 256 + lane + (i << 5)];
            s += v; q += v * v;
        }
#pragma unroll
        for (int off = 16; off > 0; off >>= 1) {
            s += __shfl_down_sync(0xffffffffu, s, off);
            q += __shfl_down_sync(0xffffffffu, q, off);
        }
        if (lane == 0) {
            atomicAdd(&g_stat1[((n << 6) + oc) * 2],     s);
            atomicAdd(&g_stat1[((n << 6) + oc) * 2 + 1], q);
        }
    }
    // y1 write, float4
    for (int idx = tid; idx < 4096; idx += 256) {
        int oc = idx >> 6;
        int r  = idx & 63;
        int y  = r >> 2;
        int xq = r & 3;
        float4 v = reinterpret_cast<float4*>(sY)[idx];
        *reinterpret_cast<float4*>(
            g_y1 + (((size_t)((n << 6) + oc)) << 16) + ((ty0 + y) << 8) + tx0 + (xq << 2)) = v;
    }
}

// ---------------------------------------------------------------------------
// K3/K6: BN coefficients. h = relu(a*x + b). pooled => batch stats (0,2,3).
// ---------------------------------------------------------------------------
__global__ void bncoef_kernel(const float* __restrict__ gamma,
                              const float* __restrict__ beta,
                              int C, int pooled, int which)
{
    int t = blockIdx.x * blockDim.x + threadIdx.x;
    if (t >= 5 * C) return;
    const float* stat = which ? g_stat2 : g_stat1;
    float* A = which ? g_a2 : g_a1;
    float* B = which ? g_b2 : g_b1;
    int o = t % C;
    float mean, var;
    if (pooled) {
        float s = 0.f, q = 0.f;
        for (int m = 0; m < 5; m++) {
            s += stat[(m * C + o) * 2];
            q += stat[(m * C + o) * 2 + 1];
        }
        const float inv = 1.f / (5.f * 65536.f);
        mean = s * inv; var = q * inv - mean * mean;
    } else {
        const float inv = 1.f / 65536.f;
        mean = stat[t * 2] * inv; var = stat[t * 2 + 1] * inv - mean * mean;
    }
    float a = gamma[o] * rsqrtf(var + 1e-5f);
    A[t] = a;
    B[t] = fmaf(-mean, a, beta[o]);
}

// ---------------------------------------------------------------------------
// K4: wmma GEMM, M=128 oc x N=128 px, K=64. Epilogue: per-frag smem scratch,
// exact stats from fp32 accs -> atomicAdd g_stat2, z written as bf16 (uint4).
// ---------------------------------------------------------------------------
#define APAD 72
#define BPAD 136
#define SCRW 20
__global__ __launch_bounds__(256) void gemm_wmma_kernel()
{
    extern __shared__ char gsmem[];
    __nv_bfloat16* sAh = reinterpret_cast<__nv_bfloat16*>(gsmem);       // 128*72
    __nv_bfloat16* sAl = sAh + 128 * APAD;
    __nv_bfloat16* sBh = sAl + 128 * APAD;                               // 16*136
    __nv_bfloat16* sBl = sBh + 16 * BPAD;
    float* s_a = reinterpret_cast<float*>(sBl + 16 * BPAD);
    float* s_b = s_a + 64;
    float* sScr = s_b + 64;                                              // 8*16*20

    const int blk = blockIdx.x;
    const int n   = blk >> 9;
    const int p0  = (blk & 511) << 7;
    const int tid = threadIdx.x;
    const int wid = tid >> 5;
    const int lane = tid & 31;
    const int warp_m = wid & 3;
    const int warp_n = wid >> 2;

    if (tid < 64) { s_a[tid] = g_a1[n * 64 + tid]; s_b[tid] = g_b1[n * 64 + tid]; }

    // stage A from pre-split w2, packed pair stores
    for (int idx = tid; idx < 128 * 32; idx += 256) {
        int oc = idx >> 5;
        int k2 = (idx & 31) << 1;
        __nv_bfloat162 a0 = g_w2s[oc * 64 + k2];
        __nv_bfloat162 a1 = g_w2s[oc * 64 + k2 + 1];
        *reinterpret_cast<__nv_bfloat162*>(&sAh[oc * APAD + k2]) = __nv_bfloat162(a0.x, a1.x);
        *reinterpret_cast<__nv_bfloat162*>(&sAl[oc * APAD + k2]) = __nv_bfloat162(a0.y, a1.y);
    }

    wmma::fragment<wmma::accumulator, 16, 16, 16, float> acc[2][4];
#pragma unroll
    for (int mi = 0; mi < 2; mi++)
#pragma unroll
        for (int j = 0; j < 4; j++) wmma::fill_fragment(acc[mi][j], 0.f);

    for (int ks = 0; ks < 4; ks++) {
        const int k0 = ks << 4;
        __syncthreads();
        for (int idx = tid; idx < 16 * 32; idx += 256) {
            int kk = idx >> 5;
            int p4 = (idx & 31) << 2;
            int o  = k0 + kk;
            float4 v = *reinterpret_cast<const float4*>(
                g_y1 + (((size_t)(n * 64 + o)) << 16) + p0 + p4);
            float a = s_a[o], bb = s_b[o];
            float hv[4] = { fmaxf(fmaf(a, v.x, bb), 0.f), fmaxf(fmaf(a, v.y, bb), 0.f),
                            fmaxf(fmaf(a, v.z, bb), 0.f), fmaxf(fmaf(a, v.w, bb), 0.f) };
            __nv_bfloat16 h0, l0, h1, l1;
            split_bf16(hv[0], h0, l0); split_bf16(hv[1], h1, l1);
            *reinterpret_cast<__nv_bfloat162*>(&sBh[kk * BPAD + p4]) = __nv_bfloat162(h0, h1);
            *reinterpret_cast<__nv_bfloat162*>(&sBl[kk * BPAD + p4]) = __nv_bfloat162(l0, l1);
            split_bf16(hv[2], h0, l0); split_bf16(hv[3], h1, l1);
            *reinterpret_cast<__nv_bfloat162*>(&sBh[kk * BPAD + p4 + 2]) = __nv_bfloat162(h0, h1);
            *reinterpret_cast<__nv_bfloat162*>(&sBl[kk * BPAD + p4 + 2]) = __nv_bfloat162(l0, l1);
        }
        __syncthreads();

        wmma::fragment<wmma::matrix_a, 16, 16, 16, __nv_bfloat16, wmma::row_major> ah[2], al[2];
#pragma unroll
        for (int mi = 0; mi < 2; mi++) {
            const int oc = (warp_m << 5) + (mi << 4);
            wmma::load_matrix_sync(ah[mi], sAh + oc * APAD + k0, APAD);
            wmma::load_matrix_sync(al[mi], sAl + oc * APAD + k0, APAD);
        }
#pragma unroll
        for (int j = 0; j < 4; j++) {
            wmma::fragment<wmma::matrix_b, 16, 16, 16, __nv_bfloat16, wmma::row_major> bh, bl;
            const int px = (warp_n << 6) + (j << 4);
            wmma::load_matrix_sync(bh, sBh + px, BPAD);
            wmma::load_matrix_sync(bl, sBl + px, BPAD);
#pragma unroll
            for (int mi = 0; mi < 2; mi++) {
                wmma::mma_sync(acc[mi][j], ah[mi], bh, acc[mi][j]);
                wmma::mma_sync(acc[mi][j], ah[mi], bl, acc[mi][j]);
                wmma::mma_sync(acc[mi][j], al[mi], bh, acc[mi][j]);
            }
        }
    }

    // epilogue: per-warp scratch, stats + bf16 z
    float* scr = sScr + wid * 16 * SCRW;
    const int ocl = lane >> 1;
    const int half = lane & 1;
#pragma unroll
    for (int mi = 0; mi < 2; mi++) {
        const int oc = (warp_m << 5) + (mi << 4) + ocl;
        float s = 0.f, q = 0.f;
#pragma unroll
        for (int j = 0; j < 4; j++) {
            wmma::store_matrix_sync(scr, acc[mi][j], SCRW, wmma::mem_row_major);
            __syncwarp();
            uint4 u;
            uint32_t* uw = reinterpret_cast<uint32_t*>(&u);
#pragma unroll
            for (int i = 0; i < 4; i++) {
                float v0 = scr[ocl * SCRW + (half << 3) + (i << 1)];
                float v1 = scr[ocl * SCRW + (half << 3) + (i << 1) + 1];
                s += v0 + v1; q += v0 * v0 + v1 * v1;
                __nv_bfloat162 pk(__float2bfloat16(v0), __float2bfloat16(v1));
                uw[i] = *reinterpret_cast<uint32_t*>(&pk);
            }
            *reinterpret_cast<uint4*>(
                g_zb + (((size_t)(n * 128 + oc)) << 16)
                     + p0 + (warp_n << 6) + (j << 4) + (half << 3)) = u;
            __syncwarp();
        }
        s += __shfl_xor_sync(0xffffffffu, s, 1);
        q += __shfl_xor_sync(0xffffffffu, q, 1);
        if (half == 0) {
            atomicAdd(&g_stat2[(n * 128 + oc) * 2],     s);
            atomicAdd(&g_stat2[(n * 128 + oc) * 2 + 1], q);
        }
    }
}

// ---------------------------------------------------------------------------
// K7: feat[e][row] = mean_pix relu(a2*z + b2), z in bf16
// ---------------------------------------------------------------------------
__global__ __launch_bounds__(256) void feat_kernel(int e)
{
    const int row = blockIdx.x;   // 0..639
    const float a = g_a2[row], b = g_b2[row];
    const __nv_bfloat162* p = reinterpret_cast<const __nv_bfloat162*>(g_zb + ((size_t)row << 16));
    float s = 0.f;
    for (int i = threadIdx.x; i < 32768; i += 256) {
        float2 v = __bfloat1622float2(p[i]);
        s += fmaxf(fmaf(a, v.x, b), 0.f) + fmaxf(fmaf(a, v.y, b), 0.f);
    }
    __shared__ float rs[256];
    rs[threadIdx.x] = s;
    __syncthreads();
    for (int st = 128; st > 0; st >>= 1) {
        if (threadIdx.x < st) rs[threadIdx.x] += rs[threadIdx.x + st];
        __syncthreads();
    }
    if (threadIdx.x == 0) g_feat[e * 640 + row] = rs[0] * (1.f / 65536.f);
}

// ---------------------------------------------------------------------------
// K8: normalize features, similarity logits, masked logsumexp CE, weighted avg
// ---------------------------------------------------------------------------
__global__ void loss_kernel(const int* __restrict__ mask, float* __restrict__ out)
{
    __shared__ float Q[3][5][128];
    __shared__ float Kf[3][5][128];
    __shared__ float S[3][5][5];
    __shared__ float X[3][5][3];
    __shared__ int cnt[12];
    __shared__ float wls[15], wts[15];
    const int tid = threadIdx.x;

    if (tid < 30) {
        int path = tid / 15;
        int r = tid % 15;
        int g = r / 5, i = r % 5;
        const float* f = g_feat + ((path * 3 + g) * 5 + i) * 128;
        float nr = 0.f;
        for (int d = 0; d < 128; d++) nr += f[d] * f[d];
        float inv = 1.f / fmaxf(sqrtf(nr), 1e-12f);
        float* dst = path ? &Kf[g][i][0] : &Q[g][i][0];
        for (int d = 0; d < 128; d++) dst[d] = f[d] * inv;
    }
    if (tid < 12) cnt[tid] = 0;
    __syncthreads();

    for (int idx = tid; idx < 4 * 128 * 128; idx += blockDim.x) {
        int m = mask[idx];
        if (m >= 1) atomicAdd(&cnt[(m - 1) * 4 + (idx >> 14)], 1);
    }

    if (tid < 75) {
        int g = tid / 25, i = (tid % 25) / 5, j = tid % 5;
        float s = 0.f;
        for (int d = 0; d < 128; d++) s += Q[g][i][d] * Kf[g][j][d];
        S[g][i][j] = s;
    } else if (tid < 120) {
        int r = tid - 75;
        int g = r / 15, i = (r % 15) / 3, h = r % 3;
        float s = 0.f;
        for (int d = 0; d < 128; d++) s += Q[g][i][d] * Kf[h][i][d];
        X[g][i][h] = s;
    }
    __syncthreads();

    if (tid < 15) {
        int g = tid / 5, i = tid % 5;
        float lg[9];
        lg[0] = S[g][i][i];
        for (int j = 0; j < 5; j++) lg[1 + j] = (j == i) ? -1e9f : S[g][i][j];
        for (int h = 0; h < 3; h++) lg[6 + h] = (h == g) ? -1e9f : X[g][i][h];
        float mx = -3.4e38f;
        for (int r = 0; r < 9; r++) { lg[r] *= 10.f; mx = fmaxf(mx, lg[r]); }
        float se = 0.f;
        for (int r = 0; r < 9; r++) se += expf(lg[r] - mx);
        float lse = mx + logf(se);
        float lt = lse - lg[0];
        float wgt = (i == 0) ? 0.f : (float)cnt[g * 4 + i - 1];
        wls[tid] = wgt * lt;
        wts[tid] = wgt;
    }
    __syncthreads();
    if (tid == 0) {
        float ws = 0.f, tot = 0.f;
        for (int r = 0; r < 15; r++) { ws += wls[r]; tot += wts[r]; }
        out[0] = (tot > 0.f) ? (ws / fmaxf(tot, 1.f)) : 0.f;
    }
}

// ---------------------------------------------------------------------------
extern "C" void kernel_launch(void* const* d_in, const int* in_sizes, int n_in,
                              void* d_out, int out_size)
{
    (void)in_sizes; (void)n_in; (void)out_size;
    const int CONV_SMEM = (2 * 18 * 18 * CPAD + 2 * 9 * 16 * WPAD) * 2;  // 72576 B
    const int GEMM_SMEM = (2 * 128 * APAD + 2 * 16 * BPAD) * 2
                        + 128 * 4 + 8 * 16 * SCRW * 4;                   // 56320 B
    static int attr_done = 0;
    if (!attr_done) {
        cudaFuncSetAttribute(conv3x3_wmma_kernel,
                             cudaFuncAttributeMaxDynamicSharedMemorySize, CONV_SMEM);
        cudaFuncSetAttribute(gemm_wmma_kernel,
                             cudaFuncAttributeMaxDynamicSharedMemorySize, GEMM_SMEM);
        attr_done = 1;
    }

    const int Cin[3] = {64, 32, 16};
    for (int g = 0; g < 3; g++) {
        const float* w1 = (const float*)d_in[g * 8 + 2];
        const float* g1 = (const float*)d_in[g * 8 + 3];
        const float* b1 = (const float*)d_in[g * 8 + 4];
        const float* w2 = (const float*)d_in[g * 8 + 5];
        const float* g2 = (const float*)d_in[g * 8 + 6];
        const float* b2 = (const float*)d_in[g * 8 + 7];

        prep_w1_kernel<<<(9 * Cin[g] * 64 + 255) / 256, 256>>>(w1, Cin[g]);
        prep_w2_kernel<<<32, 256>>>(w2);

        for (int path = 0; path < 2; path++) {
            const float* x = (const float*)d_in[g * 8 + path];

            zero_stats_kernel<<<1, 256>>>();
            conv3x3_wmma_kernel<<<1280, 256, CONV_SMEM>>>(x, Cin[g]);
            bncoef_kernel<<<2, 256>>>(g1, b1, 64, path, 0);
            gemm_wmma_kernel<<<2560, 256, GEMM_SMEM>>>();
            bncoef_kernel<<<3, 256>>>(g2, b2, 128, path, 1);
            feat_kernel<<<640, 256>>>(path * 3 + g);
        }
    }
    loss_kernel<<<1, 256>>>((const int*)d_in[24], (float*)d_out);
}

// round 17
// speedup vs baseline: 1.3959x; 1.0751x over previous
#include <cuda_runtime.h>
#include <cuda_bf16.h>
#include <mma.h>
#include <cstdint>

using namespace nvcuda;

// ---------------------------------------------------------------------------
// ContrastiveSparsityLoss — wmma bf16-split conv + GEMM, fused BN stats,
// bf16 z scratch. R17: conv patch staging packs ci-pairs into 4B STS (halves
// patch STS wavefronts); gemm stages the whole K=64 B tile once (one barrier,
// contiguous 48-MMA run) and pins 2 CTAs/SM.
// ---------------------------------------------------------------------------

__device__ float g_y1[5 * 64 * 65536];            // 83.9 MB fp32
__device__ __nv_bfloat16 g_zb[5 * 128 * 65536];   // 83.9 MB bf16
__device__ float g_stat1[5 * 64 * 2];
__device__ float g_stat2[5 * 128 * 2];
__device__ float g_a1[5 * 64];
__device__ float g_b1[5 * 64];
__device__ float g_a2[5 * 128];
__device__ float g_b2[5 * 128];
__device__ float g_feat[6 * 5 * 128];             // [e][n][oc]
__device__ __nv_bfloat162 g_w1s[9 * 64 * 64];     // [d][ci][oc] (hi,lo)
__device__ __nv_bfloat162 g_w2s[128 * 64];        // [oc][k]     (hi,lo)

__device__ __forceinline__ void split_bf16(float v, __nv_bfloat16& hi, __nv_bfloat16& lo) {
    hi = __float2bfloat16(v);
    lo = __float2bfloat16(v - __bfloat162float(hi));
}

// ---------------------------------------------------------------------------
__global__ void zero_stats_kernel()
{
    int t = threadIdx.x;
    for (int i = t; i < 640; i += 256)  g_stat1[i] = 0.f;
    for (int i = t; i < 1280; i += 256) g_stat2[i] = 0.f;
}

// prep: pre-split weights (once per granularity).
__global__ void prep_w1_kernel(const float* __restrict__ w, int Cin)
{
    int idx = blockIdx.x * blockDim.x + threadIdx.x;   // over 9*Cin*64
    if (idx >= 9 * Cin * 64) return;
    int o  = idx & 63;
    int r  = idx >> 6;          // d*Cin + ci
    int ci = r % Cin;
    int d  = r / Cin;
    __nv_bfloat16 h, l; split_bf16(w[(size_t)(o * Cin + ci) * 9 + d], h, l);
    g_w1s[idx] = __nv_bfloat162(h, l);
}
__global__ void prep_w2_kernel(const float* __restrict__ w2)
{
    int idx = blockIdx.x * blockDim.x + threadIdx.x;   // over 8192
    if (idx >= 128 * 64) return;
    __nv_bfloat16 h, l; split_bf16(w2[idx], h, l);
    g_w2s[idx] = __nv_bfloat162(h, l);
}

// ---------------------------------------------------------------------------
// K1: conv3x3 SAME via wmma. Block = 64 oc x 16x16 pixels, 2 CTAs/SM.
// Patch staged with ci-pairs packed into bf16x2 4B STS (hi/lo planes).
// ---------------------------------------------------------------------------
#define CPAD 24
#define WPAD 72
__global__ __launch_bounds__(256, 2) void conv3x3_wmma_kernel(
    const float* __restrict__ x, int Cin)
{
    extern __shared__ char dynsmem[];
    __nv_bfloat16* sPh = reinterpret_cast<__nv_bfloat16*>(dynsmem);   // [18*18][24]
    __nv_bfloat16* sPl = sPh + 18 * 18 * CPAD;
    __nv_bfloat16* sWh = sPl + 18 * 18 * CPAD;                        // [9*16][72]
    __nv_bfloat16* sWl = sWh + 9 * 16 * WPAD;

    const int b   = blockIdx.x;
    const int n   = b >> 8;
    const int t   = b & 255;
    const int ty0 = (t >> 4) << 4;
    const int tx0 = (t & 15) << 4;
    const int tid = threadIdx.x;
    const int wid = tid >> 5;
    const int lane = tid & 31;
    const int y0  = wid << 1;

    wmma::fragment<wmma::accumulator, 16, 16, 16, float> acc[2][4];
#pragma unroll
    for (int y2 = 0; y2 < 2; y2++)
#pragma unroll
        for (int f = 0; f < 4; f++) wmma::fill_fragment(acc[y2][f], 0.f);

    const int nchunks = Cin >> 4;
    for (int cb = 0; cb < nchunks; cb++) {
        const int ci0 = cb << 4;
        __syncthreads();
        // stage patch [yy*18+xx][ci]: 2 adjacent ci per thread -> 4B STS
        for (int idx = tid; idx < 8 * 324; idx += 256) {
            int cp  = idx / 324;          // ci pair 0..7
            int rem = idx - cp * 324;     // yy*18+xx
            int yy  = rem / 18;
            int xx  = rem - yy * 18;
            int gy = ty0 + yy - 1, gx = tx0 + xx - 1;
            int ci = cp << 1;
            float v0 = 0.f, v1 = 0.f;
            if ((unsigned)gy < 256u && (unsigned)gx < 256u) {
                const float* xp = x + (((size_t)(n * Cin + ci0 + ci)) << 16)
                                + (gy << 8) + gx;
                v0 = xp[0];
                v1 = xp[65536];
            }
            __nv_bfloat16 h0, l0, h1, l1;
            split_bf16(v0, h0, l0); split_bf16(v1, h1, l1);
            *reinterpret_cast<__nv_bfloat162*>(&sPh[rem * CPAD + ci]) = __nv_bfloat162(h0, h1);
            *reinterpret_cast<__nv_bfloat162*>(&sPl[rem * CPAD + ci]) = __nv_bfloat162(l0, l1);
        }
        // stage weights [d*16+ci][oc] packed pairs (4B STS)
        for (int idx = tid; idx < 9 * 16 * 32; idx += 256) {
            int d   = idx >> 9;          // /512
            int rem = idx & 511;
            int ci  = rem >> 5;
            int o2  = (rem & 31) << 1;
            __nv_bfloat162 h0 = g_w1s[(d * Cin + ci0 + ci) * 64 + o2];
            __nv_bfloat162 h1 = g_w1s[(d * Cin + ci0 + ci) * 64 + o2 + 1];
            *reinterpret_cast<__nv_bfloat162*>(&sWh[(d * 16 + ci) * WPAD + o2])
                = __nv_bfloat162(h0.x, h1.x);
            *reinterpret_cast<__nv_bfloat162*>(&sWl[(d * 16 + ci) * WPAD + o2])
                = __nv_bfloat162(h0.y, h1.y);
        }
        __syncthreads();

#pragma unroll 1
        for (int d = 0; d < 9; d++) {
            const int ky = d / 3, kx = d - 3 * (d / 3);
            wmma::fragment<wmma::matrix_b, 16, 16, 16, __nv_bfloat16, wmma::row_major> bh[4], bl[4];
#pragma unroll
            for (int f = 0; f < 4; f++) {
                wmma::load_matrix_sync(bh[f], sWh + d * 16 * WPAD + f * 16, WPAD);
                wmma::load_matrix_sync(bl[f], sWl + d * 16 * WPAD + f * 16, WPAD);
            }
#pragma unroll
            for (int y2 = 0; y2 < 2; y2++) {
                const int off = ((y0 + y2 + ky) * 18 + kx) * CPAD;
                wmma::fragment<wmma::matrix_a, 16, 16, 16, __nv_bfloat16, wmma::row_major> ah, al;
                wmma::load_matrix_sync(ah, sPh + off, CPAD);
                wmma::load_matrix_sync(al, sPl + off, CPAD);
#pragma unroll
                for (int f = 0; f < 4; f++) {
                    wmma::mma_sync(acc[y2][f], ah, bh[f], acc[y2][f]);
                    wmma::mma_sync(acc[y2][f], ah, bl[f], acc[y2][f]);
                    wmma::mma_sync(acc[y2][f], al, bh[f], acc[y2][f]);
                }
            }
        }
    }

    // epilogue: frags -> smem fp32 [oc64][y16*x16], stats + coalesced y1 write
    __syncthreads();
    float* sY = reinterpret_cast<float*>(dynsmem);   // 64 KB, aliases patch
#pragma unroll
    for (int y2 = 0; y2 < 2; y2++)
#pragma unroll
        for (int f = 0; f < 4; f++)        // element(x, ocl) -> ptr[ocl*256 + x]
            wmma::store_matrix_sync(sY + f * 16 * 256 + (y0 + y2) * 16,
                                    acc[y2][f], 256, wmma::mem_col_major);
    __syncthreads();

    // stats: warp w owns oc rows 8w..8w+7 (256 px each)
#pragma unroll
    for (int u = 0; u < 8; u++) {
        const int oc = (wid << 3) + u;
        float s = 0.f, q = 0.f;
#pragma unroll
        for (int i = 0; i < 8; i++) {
            float v = sY[oc * 256 + lane + (i << 5)];
            s += v; q += v * v;
        }
#pragma unroll
        for (int off = 16; off > 0; off >>= 1) {
            s += __shfl_down_sync(0xffffffffu, s, off);
            q += __shfl_down_sync(0xffffffffu, q, off);
        }
        if (lane == 0) {
            atomicAdd(&g_stat1[((n << 6) + oc) * 2],     s);
            atomicAdd(&g_stat1[((n << 6) + oc) * 2 + 1], q);
        }
    }
    // y1 write, float4
    for (int idx = tid; idx < 4096; idx += 256) {
        int oc = idx >> 6;
        int r  = idx & 63;
        int y  = r >> 2;
        int xq = r & 3;
        float4 v = reinterpret_cast<float4*>(sY)[idx];
        *reinterpret_cast<float4*>(
            g_y1 + (((size_t)((n << 6) + oc)) << 16) + ((ty0 + y) << 8) + tx0 + (xq << 2)) = v;
    }
}

// ---------------------------------------------------------------------------
// K3/K6: BN coefficients. h = relu(a*x + b). pooled => batch stats (0,2,3).
// ---------------------------------------------------------------------------
__global__ void bncoef_kernel(const float* __restrict__ gamma,
                              const float* __restrict__ beta,
                              int C, int pooled, int which)
{
    int t = blockIdx.x * blockDim.x + threadIdx.x;
    if (t >= 5 * C) return;
    const float* stat = which ? g_stat2 : g_stat1;
    float* A = which ? g_a2 : g_a1;
    float* B = which ? g_b2 : g_b1;
    int o = t % C;
    float mean, var;
    if (pooled) {
        float s = 0.f, q = 0.f;
        for (int m = 0; m < 5; m++) {
            s += stat[(m * C + o) * 2];
            q += stat[(m * C + o) * 2 + 1];
        }
        const float inv = 1.f / (5.f * 65536.f);
        mean = s * inv; var = q * inv - mean * mean;
    } else {
        const float inv = 1.f / 65536.f;
        mean = stat[t * 2] * inv; var = stat[t * 2 + 1] * inv - mean * mean;
    }
    float a = gamma[o] * rsqrtf(var + 1e-5f);
    A[t] = a;
    B[t] = fmaf(-mean, a, beta[o]);
}

// ---------------------------------------------------------------------------
// K4: wmma GEMM, M=128 oc x N=128 px, K=64 staged whole (one barrier).
// Epilogue: per-frag smem scratch, exact stats, z written as bf16 (uint4).
// ---------------------------------------------------------------------------
#define APAD 72
#define BPAD 136
#define SCRW 20
__global__ __launch_bounds__(256, 2) void gemm_wmma_kernel()
{
    extern __shared__ char gsmem[];
    __nv_bfloat16* sAh = reinterpret_cast<__nv_bfloat16*>(gsmem);       // 128*72
    __nv_bfloat16* sAl = sAh + 128 * APAD;
    __nv_bfloat16* sBh = sAl + 128 * APAD;                               // 64*136
    __nv_bfloat16* sBl = sBh + 64 * BPAD;
    float* s_a = reinterpret_cast<float*>(sBl + 64 * BPAD);
    float* s_b = s_a + 64;
    float* sScr = s_b + 64;                                              // 8*16*20

    const int blk = blockIdx.x;
    const int n   = blk >> 9;
    const int p0  = (blk & 511) << 7;
    const int tid = threadIdx.x;
    const int wid = tid >> 5;
    const int lane = tid & 31;
    const int warp_m = wid & 3;
    const int warp_n = wid >> 2;

    if (tid < 64) { s_a[tid] = g_a1[n * 64 + tid]; s_b[tid] = g_b1[n * 64 + tid]; }

    // stage A from pre-split w2, packed pair stores
    for (int idx = tid; idx < 128 * 32; idx += 256) {
        int oc = idx >> 5;
        int k2 = (idx & 31) << 1;
        __nv_bfloat162 a0 = g_w2s[oc * 64 + k2];
        __nv_bfloat162 a1 = g_w2s[oc * 64 + k2 + 1];
        *reinterpret_cast<__nv_bfloat162*>(&sAh[oc * APAD + k2]) = __nv_bfloat162(a0.x, a1.x);
        *reinterpret_cast<__nv_bfloat162*>(&sAl[oc * APAD + k2]) = __nv_bfloat162(a0.y, a1.y);
    }
    __syncthreads();   // s_a/s_b visible for B staging

    // stage ALL of B: h = relu(a*y1+b), k rows 0..63, 128 px
    for (int idx = tid; idx < 64 * 32; idx += 256) {
        int o  = idx >> 5;
        int p4 = (idx & 31) << 2;
        float4 v = *reinterpret_cast<const float4*>(
            g_y1 + (((size_t)(n * 64 + o)) << 16) + p0 + p4);
        float a = s_a[o], bb = s_b[o];
        float hv[4] = { fmaxf(fmaf(a, v.x, bb), 0.f), fmaxf(fmaf(a, v.y, bb), 0.f),
                        fmaxf(fmaf(a, v.z, bb), 0.f), fmaxf(fmaf(a, v.w, bb), 0.f) };
        __nv_bfloat16 h0, l0, h1, l1;
        split_bf16(hv[0], h0, l0); split_bf16(hv[1], h1, l1);
        *reinterpret_cast<__nv_bfloat162*>(&sBh[o * BPAD + p4]) = __nv_bfloat162(h0, h1);
        *reinterpret_cast<__nv_bfloat162*>(&sBl[o * BPAD + p4]) = __nv_bfloat162(l0, l1);
        split_bf16(hv[2], h0, l0); split_bf16(hv[3], h1, l1);
        *reinterpret_cast<__nv_bfloat162*>(&sBh[o * BPAD + p4 + 2]) = __nv_bfloat162(h0, h1);
        *reinterpret_cast<__nv_bfloat162*>(&sBl[o * BPAD + p4 + 2]) = __nv_bfloat162(l0, l1);
    }
    __syncthreads();

    wmma::fragment<wmma::accumulator, 16, 16, 16, float> acc[2][4];
#pragma unroll
    for (int mi = 0; mi < 2; mi++)
#pragma unroll
        for (int j = 0; j < 4; j++) wmma::fill_fragment(acc[mi][j], 0.f);

#pragma unroll 1
    for (int ks = 0; ks < 4; ks++) {
        const int k0 = ks << 4;
        wmma::fragment<wmma::matrix_a, 16, 16, 16, __nv_bfloat16, wmma::row_major> ah[2], al[2];
#pragma unroll
        for (int mi = 0; mi < 2; mi++) {
            const int oc = (warp_m << 5) + (mi << 4);
            wmma::load_matrix_sync(ah[mi], sAh + oc * APAD + k0, APAD);
            wmma::load_matrix_sync(al[mi], sAl + oc * APAD + k0, APAD);
        }
#pragma unroll
        for (int j = 0; j < 4; j++) {
            wmma::fragment<wmma::matrix_b, 16, 16, 16, __nv_bfloat16, wmma::row_major> bh, bl;
            const int px = (warp_n << 6) + (j << 4);
            wmma::load_matrix_sync(bh, sBh + k0 * BPAD + px, BPAD);
            wmma::load_matrix_sync(bl, sBl + k0 * BPAD + px, BPAD);
#pragma unroll
            for (int mi = 0; mi < 2; mi++) {
                wmma::mma_sync(acc[mi][j], ah[mi], bh, acc[mi][j]);
                wmma::mma_sync(acc[mi][j], ah[mi], bl, acc[mi][j]);
                wmma::mma_sync(acc[mi][j], al[mi], bh, acc[mi][j]);
            }
        }
    }

    // epilogue: per-warp scratch, stats + bf16 z
    float* scr = sScr + wid * 16 * SCRW;
    const int ocl = lane >> 1;
    const int half = lane & 1;
#pragma unroll
    for (int mi = 0; mi < 2; mi++) {
        const int oc = (warp_m << 5) + (mi << 4) + ocl;
        float s = 0.f, q = 0.f;
#pragma unroll
        for (int j = 0; j < 4; j++) {
            wmma::store_matrix_sync(scr, acc[mi][j], SCRW, wmma::mem_row_major);
            __syncwarp();
            uint4 u;
            uint32_t* uw = reinterpret_cast<uint32_t*>(&u);
#pragma unroll
            for (int i = 0; i < 4; i++) {
                float v0 = scr[ocl * SCRW + (half << 3) + (i << 1)];
                float v1 = scr[ocl * SCRW + (half << 3) + (i << 1) + 1];
                s += v0 + v1; q += v0 * v0 + v1 * v1;
                __nv_bfloat162 pk(__float2bfloat16(v0), __float2bfloat16(v1));
                uw[i] = *reinterpret_cast<uint32_t*>(&pk);
            }
            *reinterpret_cast<uint4*>(
                g_zb + (((size_t)(n * 128 + oc)) << 16)
                     + p0 + (warp_n << 6) + (j << 4) + (half << 3)) = u;
            __syncwarp();
        }
        s += __shfl_xor_sync(0xffffffffu, s, 1);
        q += __shfl_xor_sync(0xffffffffu, q, 1);
        if (half == 0) {
            atomicAdd(&g_stat2[(n * 128 + oc) * 2],     s);
            atomicAdd(&g_stat2[(n * 128 + oc) * 2 + 1], q);
        }
    }
}

// ---------------------------------------------------------------------------
// K7: feat[e][row] = mean_pix relu(a2*z + b2), z in bf16
// ---------------------------------------------------------------------------
__global__ __launch_bounds__(256) void feat_kernel(int e)
{
    const int row = blockIdx.x;   // 0..639
    const float a = g_a2[row], b = g_b2[row];
    const __nv_bfloat162* p = reinterpret_cast<const __nv_bfloat162*>(g_zb + ((size_t)row << 16));
    float s = 0.f;
    for (int i = threadIdx.x; i < 32768; i += 256) {
        float2 v = __bfloat1622float2(p[i]);
        s += fmaxf(fmaf(a, v.x, b), 0.f) + fmaxf(fmaf(a, v.y, b), 0.f);
    }
    __shared__ float rs[256];
    rs[threadIdx.x] = s;
    __syncthreads();
    for (int st = 128; st > 0; st >>= 1) {
        if (threadIdx.x < st) rs[threadIdx.x] += rs[threadIdx.x + st];
        __syncthreads();
    }
    if (threadIdx.x == 0) g_feat[e * 640 + row] = rs[0] * (1.f / 65536.f);
}

// ---------------------------------------------------------------------------
// K8: normalize features, similarity logits, masked logsumexp CE, weighted avg
// ---------------------------------------------------------------------------
__global__ void loss_kernel(const int* __restrict__ mask, float* __restrict__ out)
{
    __shared__ float Q[3][5][128];
    __shared__ float Kf[3][5][128];
    __shared__ float S[3][5][5];
    __shared__ float X[3][5][3];
    __shared__ int cnt[12];
    __shared__ float wls[15], wts[15];
    const int tid = threadIdx.x;

    if (tid < 30) {
        int path = tid / 15;
        int r = tid % 15;
        int g = r / 5, i = r % 5;
        const float* f = g_feat + ((path * 3 + g) * 5 + i) * 128;
        float nr = 0.f;
        for (int d = 0; d < 128; d++) nr += f[d] * f[d];
        float inv = 1.f / fmaxf(sqrtf(nr), 1e-12f);
        float* dst = path ? &Kf[g][i][0] : &Q[g][i][0];
        for (int d = 0; d < 128; d++) dst[d] = f[d] * inv;
    }
    if (tid < 12) cnt[tid] = 0;
    __syncthreads();

    for (int idx = tid; idx < 4 * 128 * 128; idx += blockDim.x) {
        int m = mask[idx];
        if (m >= 1) atomicAdd(&cnt[(m - 1) * 4 + (idx >> 14)], 1);
    }

    if (tid < 75) {
        int g = tid / 25, i = (tid % 25) / 5, j = tid % 5;
        float s = 0.f;
        for (int d = 0; d < 128; d++) s += Q[g][i][d] * Kf[g][j][d];
        S[g][i][j] = s;
    } else if (tid < 120) {
        int r = tid - 75;
        int g = r / 15, i = (r % 15) / 3, h = r % 3;
        float s = 0.f;
        for (int d = 0; d < 128; d++) s += Q[g][i][d] * Kf[h][i][d];
        X[g][i][h] = s;
    }
    __syncthreads();

    if (tid < 15) {
        int g = tid / 5, i = tid % 5;
        float lg[9];
        lg[0] = S[g][i][i];
        for (int j = 0; j < 5; j++) lg[1 + j] = (j == i) ? -1e9f : S[g][i][j];
        for (int h = 0; h < 3; h++) lg[6 + h] = (h == g) ? -1e9f : X[g][i][h];
        float mx = -3.4e38f;
        for (int r = 0; r < 9; r++) { lg[r] *= 10.f; mx = fmaxf(mx, lg[r]); }
        float se = 0.f;
        for (int r = 0; r < 9; r++) se += expf(lg[r] - mx);
        float lse = mx + logf(se);
        float lt = lse - lg[0];
        float wgt = (i == 0) ? 0.f : (float)cnt[g * 4 + i - 1];
        wls[tid] = wgt * lt;
        wts[tid] = wgt;
    }
    __syncthreads();
    if (tid == 0) {
        float ws = 0.f, tot = 0.f;
        for (int r = 0; r < 15; r++) { ws += wls[r]; tot += wts[r]; }
        out[0] = (tot > 0.f) ? (ws / fmaxf(tot, 1.f)) : 0.f;
    }
}

// ---------------------------------------------------------------------------
extern "C" void kernel_launch(void* const* d_in, const int* in_sizes, int n_in,
                              void* d_out, int out_size)
{
    (void)in_sizes; (void)n_in; (void)out_size;
    const int CONV_SMEM = (2 * 18 * 18 * CPAD + 2 * 9 * 16 * WPAD) * 2;  // 72576 B
    const int GEMM_SMEM = (2 * 128 * APAD + 2 * 64 * BPAD) * 2
                        + 128 * 4 + 8 * 16 * SCRW * 4;                   // 82432 B
    static int attr_done = 0;
    if (!attr_done) {
        cudaFuncSetAttribute(conv3x3_wmma_kernel,
                             cudaFuncAttributeMaxDynamicSharedMemorySize, CONV_SMEM);
        cudaFuncSetAttribute(gemm_wmma_kernel,
                             cudaFuncAttributeMaxDynamicSharedMemorySize, GEMM_SMEM);
        attr_done = 1;
    }

    const int Cin[3] = {64, 32, 16};
    for (int g = 0; g < 3; g++) {
        const float* w1 = (const float*)d_in[g * 8 + 2];
        const float* g1 = (const float*)d_in[g * 8 + 3];
        const float* b1 = (const float*)d_in[g * 8 + 4];
        const float* w2 = (const float*)d_in[g * 8 + 5];
        const float* g2 = (const float*)d_in[g * 8 + 6];
        const float* b2 = (const float*)d_in[g * 8 + 7];

        prep_w1_kernel<<<(9 * Cin[g] * 64 + 255) / 256, 256>>>(w1, Cin[g]);
        prep_w2_kernel<<<32, 256>>>(w2);

        for (int path = 0; path < 2; path++) {
            const float* x = (const float*)d_in[g * 8 + path];

            zero_stats_kernel<<<1, 256>>>();
            conv3x3_wmma_kernel<<<1280, 256, CONV_SMEM>>>(x, Cin[g]);
            bncoef_kernel<<<2, 256>>>(g1, b1, 64, path, 0);
            gemm_wmma_kernel<<<2560, 256, GEMM_SMEM>>>();
            bncoef_kernel<<<3, 256>>>(g2, b2, 128, path, 1);
            feat_kernel<<<640, 256>>>(path * 3 + g);
        }
    }
    loss_kernel<<<1, 256>>>((const int*)d_in[24], (float*)d_out);
}